// round 17
// baseline (speedup 1.0000x reference)
#include <cuda_runtime.h>
#include <cuda_bf16.h>
#include <cstdint>

// x: (128, 512, 14, 14) fp32 ; W: (20, 512) fp32
#define NT   128
#define CCH  512
#define HWS  196
#define TT   8
#define NN   16
#define HH   4
#define KK   5
#define OO   20
#define BB   3136   // NN * HWS

// scratch: softmax weights, layout [h][t][k][B]
__device__ float g_weights[(size_t)HH * TT * KK * BB];
#define GW_IDX(h, t, k, b) ((((size_t)(h) * TT + (t)) * KK + (k)) * BB + (b))

// ---------------- kernel 1: TF32 MMA, TMA-bulk staged A ---------------------
// grid = 256: bid = nt*2 + half. 256 threads (8 warps).
// A staged via cp.async.bulk (TMA pipe, 1 instr per 384/400B row) -> kills the
// LDGSTS 8cyc/op issue ceiling that pinned K1 at ~20us.
#define KC      32
#define NCHUNK  16
#define NBUF    2
#define APITCH  104                   // floats; 416B rows (16B-aligned)
#define ABUF    (KC * APITCH)
#define WTP     20
// floats: A-bufs + Wt + 16 guard; then 2 mbarriers (16B)
#define MBAR_FOFF (NBUF * ABUF + CCH * WTP + 16)
#define SMEM1_BYTES (MBAR_FOFF * 4 + 16)

__device__ __forceinline__ uint32_t smem_u32(const void* p) {
    uint32_t a;
    asm("{ .reg .u64 t; cvta.to.shared.u64 t, %1; cvt.u32.u64 %0, t; }"
        : "=r"(a) : "l"(p));
    return a;
}

#define MMA_TF32(d, a0, a1, a2, a3, b0, b1)                                   \
    asm volatile("mma.sync.aligned.m16n8k8.row.col.f32.tf32.tf32.f32 "        \
                 "{%0,%1,%2,%3}, {%4,%5,%6,%7}, {%8,%9}, {%0,%1,%2,%3};"      \
                 : "+f"(d[0]), "+f"(d[1]), "+f"(d[2]), "+f"(d[3])             \
                 : "r"(a0), "r"(a1), "r"(a2), "r"(a3), "r"(b0), "r"(b1))

#define MBAR_INIT(addr, cnt)                                                  \
    asm volatile("mbarrier.init.shared.b64 [%0], %1;"                         \
                 :: "r"(addr), "r"(cnt) : "memory")
#define MBAR_EXPECT_TX(addr, bytes)                                           \
    asm volatile("mbarrier.arrive.expect_tx.shared.b64 _, [%0], %1;"          \
                 :: "r"(addr), "r"(bytes) : "memory")
#define MBAR_WAIT(addr, parity) do {                                          \
    uint32_t _done = 0;                                                       \
    while (!_done) {                                                          \
        asm volatile("{\n\t.reg .pred p;\n\t"                                 \
            "mbarrier.try_wait.parity.acquire.cta.shared::cta.b64 p, [%1], %2;\n\t" \
            "selp.b32 %0, 1, 0, p;\n\t}"                                      \
            : "=r"(_done) : "r"(addr), "r"(parity) : "memory");               \
    }                                                                         \
} while (0)

#define BULK_CP(daddr, saddr, bytes, mbar)                                    \
    asm volatile("cp.async.bulk.shared::cta.global.mbarrier::complete_tx::bytes " \
                 "[%0], [%1], %2, [%3];"                                      \
                 :: "r"(daddr), "l"((const void*)(saddr)), "r"(bytes), "r"(mbar) \
                 : "memory")

__global__ void __launch_bounds__(256)
weights_mma_kernel(const float* __restrict__ x, const float* __restrict__ W)
{
    extern __shared__ float smem[];
    float* Abuf = smem;                    // [2][KC][APITCH]
    float* Wt   = smem + NBUF * ABUF;      // [512][20] (+16f guard)

    const int tid  = threadIdx.x;
    const int bid  = blockIdx.x;
    const int nt   = bid >> 1;             // image 0..127
    const int half = bid & 1;
    const int off  = half * 96;
    const int nsp  = half ? 100 : 96;
    const int ntiles = half ? 7 : 6;

    const int w  = tid >> 5;
    const int l  = tid & 31;
    const int lg = l >> 2;
    const int lc = l & 3;

    // stage W transposed (raw fp32; mma HW truncates to tf32)
    for (int i = tid; i < OO * CCH; i += 256) {
        const int n = i >> 9, k = i & (CCH - 1);
        Wt[k * WTP + n] = W[i];
    }

    const float* xbase = x + (size_t)nt * CCH * HWS + off;
    const uint32_t abase_u32 = smem_u32(Abuf);
    const uint32_t mbar0 = smem_u32(smem + MBAR_FOFF);
    const uint32_t mbar1 = mbar0 + 8;
    const int rowbytes   = nsp * 4;        // 384 or 400 (16B multiples)

    if (tid == 0) { MBAR_INIT(mbar0, 1); MBAR_INIT(mbar1, 1); }
    __syncthreads();                       // Wt visible + mbarriers ready

    // stage chunk ck into buffer ck&1 (thread 0 only)
    auto stage = [&](int ck) {
        const uint32_t mb = (ck & 1) ? mbar1 : mbar0;
        const float* src = xbase + (size_t)ck * KC * HWS;
        const uint32_t dst0 = abase_u32 + (ck & 1) * (ABUF * 4);
        MBAR_EXPECT_TX(mb, KC * rowbytes);
#pragma unroll 4
        for (int c = 0; c < KC; ++c)
            BULK_CP(dst0 + c * (APITCH * 4), src + (size_t)c * HWS, rowbytes, mb);
    };

    if (tid == 0) { stage(0); stage(1); }

    const bool tvalid = (w < ntiles);
    const int sp0 = 16 * w + lg;
    const int spa = min(sp0, APITCH - 1);
    const int spb = min(sp0 + 8, APITCH - 1);

    float d[3][4];
#pragma unroll
    for (int nf = 0; nf < 3; ++nf)
#pragma unroll
        for (int r = 0; r < 4; ++r) d[nf][r] = 0.f;

    int ph0 = 0, ph1 = 0;                  // per-buffer wait parity

    for (int ck = 0; ck < NCHUNK; ++ck) {
        if (ck & 1) { MBAR_WAIT(mbar1, ph1); ph1 ^= 1; }
        else        { MBAR_WAIT(mbar0, ph0); ph0 ^= 1; }

        const float* Ab = Abuf + (ck & 1) * ABUF;
#pragma unroll
        for (int k8 = 0; k8 < KC / 8; ++k8) {
            const int kl = k8 * 8;
            const int kg = ck * KC + kl + lc;
            uint32_t bfr[3][2];
#pragma unroll
            for (int nf = 0; nf < 3; ++nf) {
                bfr[nf][0] = __float_as_uint(Wt[kg * WTP + 8 * nf + lg]);
                bfr[nf][1] = __float_as_uint(Wt[(kg + 4) * WTP + 8 * nf + lg]);
            }
            if (tvalid) {
                const float* r0 = Ab + (kl + lc) * APITCH;
                const float* r4 = Ab + (kl + lc + 4) * APITCH;
                const uint32_t a0 = __float_as_uint(r0[spa]);
                const uint32_t a1 = __float_as_uint(r0[spb]);
                const uint32_t a2 = __float_as_uint(r4[spa]);
                const uint32_t a3 = __float_as_uint(r4[spb]);
#pragma unroll
                for (int nf = 0; nf < 3; ++nf)
                    MMA_TF32(d[nf], a0, a1, a2, a3, bfr[nf][0], bfr[nf][1]);
            }
        }
        __syncthreads();                   // all threads done with this buffer
        if (tid == 0 && ck + 2 < NCHUNK) stage(ck + 2);
    }

    // exchange D through smem (overwrite Abuf): Dx[112][24]
    float* Dx = smem;
    if (tvalid) {
        const int r = 16 * w + lg;
#pragma unroll
        for (int nf = 0; nf < 3; ++nf) {
            const int col = nf * 8 + 2 * lc;
            Dx[r * 24 + col]           = d[nf][0];
            Dx[r * 24 + col + 1]       = d[nf][1];
            Dx[(r + 8) * 24 + col]     = d[nf][2];
            Dx[(r + 8) * 24 + col + 1] = d[nf][3];
        }
    }
    __syncthreads();

    const int t_  = nt & (TT - 1);
    const int n_i = nt >> 3;
    for (int s = tid; s < nsp; s += 256) {
        const float* row = Dx + s * 24;
        const int b = n_i * HWS + off + s;
#pragma unroll
        for (int h = 0; h < HH; ++h) {
            float lo[KK];
#pragma unroll
            for (int k = 0; k < KK; ++k) lo[k] = row[h * KK + k];
            float m = lo[0];
#pragma unroll
            for (int k = 1; k < KK; ++k) m = fmaxf(m, lo[k]);
            float e[KK], sum = 0.f;
#pragma unroll
            for (int k = 0; k < KK; ++k) { e[k] = __expf(lo[k] - m); sum += e[k]; }
            const float inv = 1.f / sum;
#pragma unroll
            for (int k = 0; k < KK; ++k)
                g_weights[GW_IDX(h, t_, k, b)] = e[k] * inv;
        }
    }
}

// ---------------- kernel 2: causal 5-tap combine (R11 exact, 17.7us) --------
__global__ void __launch_bounds__(224)
combine_kernel(const float* __restrict__ x, float* __restrict__ out)
{
    const int n_i = blockIdx.x;
    const int ct  = blockIdx.y;           // channel tile of 8
    const int h   = ct >> 4;

    const int sp = threadIdx.x;
    if (sp >= HWS) return;

    const int b = n_i * HWS + sp;
    float wt[TT * KK];
#pragma unroll
    for (int t = 0; t < TT; ++t)
#pragma unroll
        for (int k = 0; k < KK; ++k)
            wt[t * KK + k] = g_weights[GW_IDX(h, t, k, b)];

    const size_t tstride = (size_t)CCH * HWS;
    const size_t base = ((size_t)n_i * TT * CCH + (size_t)ct * 8) * HWS + sp;

#pragma unroll
    for (int cp = 0; cp < 4; ++cp) {
        const float* xp0 = x + base + (size_t)(2 * cp) * HWS;
        const float* xp1 = xp0 + HWS;
        float a[TT], bv[TT];
#pragma unroll
        for (int t = 0; t < TT; ++t) a[t]  = xp0[(size_t)t * tstride];
#pragma unroll
        for (int t = 0; t < TT; ++t) bv[t] = xp1[(size_t)t * tstride];

        float* op0 = out + base + (size_t)(2 * cp) * HWS;
        float* op1 = op0 + HWS;
#pragma unroll
        for (int t = 0; t < TT; ++t) {
            float s0 = 0.f, s1 = 0.f;
#pragma unroll
            for (int k = 0; k < KK; ++k) {
                const int src = t + k - 4;
                if (src >= 0) {
                    s0 = fmaf(wt[t * KK + k], a[src],  s0);
                    s1 = fmaf(wt[t * KK + k], bv[src], s1);
                }
            }
            op0[(size_t)t * tstride] = s0;
            op1[(size_t)t * tstride] = s1;
        }
    }
}

// ---------------------------------------------------------------------------
extern "C" void kernel_launch(void* const* d_in, const int* in_sizes, int n_in,
                              void* d_out, int out_size)
{
    const float* x = (const float*)d_in[0];
    const float* W = (const float*)d_in[1];
    float* out = (float*)d_out;

    cudaFuncSetAttribute(weights_mma_kernel,
                         cudaFuncAttributeMaxDynamicSharedMemorySize, SMEM1_BYTES);

    weights_mma_kernel<<<2 * NT, 256, SMEM1_BYTES>>>(x, W);
    combine_kernel<<<dim3(NN, 64), 224>>>(x, out);
}